// round 6
// baseline (speedup 1.0000x reference)
#include <cuda_runtime.h>
#include <cuda_fp16.h>

#define W 960
#define H 512
#define C 16
#define HW (H * W)
#define WP (W / 2)           /* 480 pixel-pairs per image row */

// pair-packed fp16 image: uint4 index = pairIdx*4 + cg,
// payload = 8 halves: [pixEven ch0..3, pixOdd ch0..3]
__device__ uint4 g_h4[HW * 2];

// ---------------- transpose+pack CHW fp32 -> pair-packed fp16 ----------------
#define TP_PIX 128
__global__ __launch_bounds__(256) void transpose_kernel(const float* __restrict__ img)
{
    __shared__ float tile[TP_PIX][C + 1];
    const int pix0 = blockIdx.x * TP_PIX;

#pragma unroll
    for (int i = 0; i < 2; i++) {
        const int idx = threadIdx.x + i * 256;     // 512 float4 loads
        const int c = idx >> 5;                    // channel
        const int v = idx & 31;                    // float4 within row
        const float4 d = *(const float4*)(img + c * HW + pix0 + v * 4);
        tile[v * 4 + 0][c] = d.x;
        tile[v * 4 + 1][c] = d.y;
        tile[v * 4 + 2][c] = d.z;
        tile[v * 4 + 3][c] = d.w;
    }
    __syncthreads();

    {
        const int p2l = threadIdx.x >> 2;          // 0..63 local pair
        const int cg  = threadIdx.x & 3;
        const float* re = tile[p2l * 2 + 0];
        const float* ro = tile[p2l * 2 + 1];
        __half2 e01 = __floats2half2_rn(re[cg*4+0], re[cg*4+1]);
        __half2 e23 = __floats2half2_rn(re[cg*4+2], re[cg*4+3]);
        __half2 o01 = __floats2half2_rn(ro[cg*4+0], ro[cg*4+1]);
        __half2 o23 = __floats2half2_rn(ro[cg*4+2], ro[cg*4+3]);
        uint4 v;
        v.x = *reinterpret_cast<unsigned*>(&e01);
        v.y = *reinterpret_cast<unsigned*>(&e23);
        v.z = *reinterpret_cast<unsigned*>(&o01);
        v.w = *reinterpret_cast<unsigned*>(&o23);
        g_h4[((pix0 >> 1) + p2l) * 4 + cg] = v;
    }
}

// ---------------- scatter-patch reconstruct ----------------
#define TILE 16
#define HALO 18
#define NUNIT (HALO * HALO)   /* 324 */
#define NWAVE 6
#define ACC_PITCH 257
#define UPS 9                 /* float4 slots per unit (144B, conflict-free) */

__global__ __launch_bounds__(256, 2) void recon_scatter(
    const float* __restrict__ offx,
    const float* __restrict__ offy,
    float* __restrict__ out)
{
    __shared__ float4 acc[4][ACC_PITCH];
    __shared__ float4 up[NUNIT * UPS];
    float* upf = (float*)up;

    const int tid = threadIdx.x;
    const int h0 = blockIdx.y * TILE;
    const int w0 = blockIdx.x * TILE;

    for (int i = tid; i < 4 * ACC_PITCH; i += 256)
        ((float4*)acc)[i] = make_float4(0.f, 0.f, 0.f, 0.f);

    // ---------- phase A: per-unit params ----------
    // layout (36 floats): [0..8] we[dj*3+j], [9..17] wo[dj*3+j],
    // [18..29] wy[di*4+r], [30] baseq, [31] need3, [32..35] pad
    for (int u = tid; u < NUNIT; u += 256) {
        const int ur = u / HALO, uc = u % HALO;
        const int hh = h0 - 1 + ur, ww = w0 - 1 + uc;
        float fb[32];
#pragma unroll
        for (int k = 0; k < 32; k++) fb[k] = 0.f;

        if (hh >= 0 && hh < H && ww >= 0 && ww < W) {
            const float sx = __ldg(offx + hh * W + ww);
            const float sy = __ldg(offy + hh * W + ww);

            // ---- x ----
            int x0a[3]; float fxa[3], ma[3]; int pmin = W;
#pragma unroll
            for (int dj = 0; dj < 3; dj++) {
                const int wt = ww + 1 - dj;
                float m = (wt >= 0 && wt < W) ? 1.f : 0.f;
                if (ww == 1     && wt == 0    ) m += 1.f;
                if (ww == W - 2 && wt == W - 1) m += 1.f;
                float cx  = fminf(fmaxf((float)wt - sx, 0.f), (float)(W - 1));
                float ix  = cx * ((float)(W - 1) / (float)W);
                float x0f = floorf(ix);
                x0a[dj] = (int)x0f; fxa[dj] = ix - x0f; ma[dj] = m;
                if (m != 0.f) pmin = min(pmin, x0a[dj]);
            }
            const int px2 = min(pmin & ~1, W - 6);   // even window start, 6 wide
            int lmax = 0;
#pragma unroll
            for (int dj = 0; dj < 3; dj++) {
                const int l = min(max(x0a[dj] - px2, 0), 4);
                if (ma[dj] != 0.f) lmax = max(lmax, l);
                float v[6];
#pragma unroll
                for (int c = 0; c < 6; c++)
                    v[c] = ma[dj] * ((c == l) ? (1.f - fxa[dj])
                                   : ((c == l + 1) ? fxa[dj] : 0.f));
#pragma unroll
                for (int j = 0; j < 3; j++) {
                    fb[dj * 3 + j]     = v[2 * j];      // even-pixel weight
                    fb[9 + dj * 3 + j] = v[2 * j + 1];  // odd-pixel weight
                }
            }

            // ---- y ----
            int y0a[3]; float fya[3], mya[3]; int qmin = H;
#pragma unroll
            for (int di = 0; di < 3; di++) {
                const int ht = hh + 1 - di;
                float m = (ht >= 0 && ht < H) ? 1.f : 0.f;
                if (hh == 1     && ht == 0    ) m += 1.f;
                if (hh == H - 2 && ht == H - 1) m += 1.f;
                float cy  = fminf(fmaxf((float)ht - sy, 0.f), (float)(H - 1));
                float iy  = cy * ((float)(H - 1) / (float)H);
                float y0f = floorf(iy);
                y0a[di] = (int)y0f; fya[di] = iy - y0f; mya[di] = m;
                if (m != 0.f) qmin = min(qmin, y0a[di]);
            }
            const int py = min(qmin, H - 4);
#pragma unroll
            for (int di = 0; di < 3; di++) {
                const int l = min(max(y0a[di] - py, 0), 2);
#pragma unroll
                for (int r = 0; r < 4; r++)
                    fb[18 + di * 4 + r] = mya[di] * ((r == l) ? (1.f - fya[di])
                                         : ((r == l + 1) ? fya[di] : 0.f));
            }
            fb[30] = __int_as_float(py * WP + (px2 >> 1));  // base pair index
            fb[31] = (lmax >= 3) ? 1.f : 0.f;               // need 3rd pair
        }
#pragma unroll
        for (int k = 0; k < 32; k++) upf[u * (UPS * 4) + k] = fb[k];
    }
    __syncthreads();

    // ---------- phase B ----------
    const int cg = tid & 3;

    for (int wave = 0; wave < NWAVE; wave++) {
        const int u = wave * 64 + (tid >> 2);
        const bool has = (u < NUNIT);
        const int uu = has ? u : 0;

        const float4 s0 = up[uu * UPS + 0];
        const float4 s1 = up[uu * UPS + 1];
        const float4 s2 = up[uu * UPS + 2];
        const float4 s3 = up[uu * UPS + 3];
        const float4 s4 = up[uu * UPS + 4];
        const float4 s5 = up[uu * UPS + 5];
        const float4 s6 = up[uu * UPS + 6];
        const float4 s7 = up[uu * UPS + 7];

        // unpack
        const float we[3][3] = {{s0.x, s0.y, s0.z}, {s0.w, s1.x, s1.y}, {s1.z, s1.w, s2.x}};
        const float wo[3][3] = {{s2.y, s2.z, s2.w}, {s3.x, s3.y, s3.z}, {s3.w, s4.x, s4.y}};
        const float wy[3][4] = {{s4.z, s4.w, s5.x, s5.y},
                                {s5.z, s5.w, s6.x, s6.y},
                                {s6.z, s6.w, s7.x, s7.y}};
        const int baseq = __float_as_int(s7.z);
        const bool need3 = (s7.w != 0.f);
        const int ur = uu / HALO, uc = uu % HALO;

        const float4 z = make_float4(0.f, 0.f, 0.f, 0.f);
        float4 o[9] = {z, z, z, z, z, z, z, z, z};

#pragma unroll
        for (int r = 0; r < 4; r++) {
            const int qb = (baseq + r * WP) * 4 + cg;
            uint4 P[3];
            P[0] = __ldg(g_h4 + qb);
            P[1] = __ldg(g_h4 + qb + 4);
            if (need3) P[2] = __ldg(g_h4 + qb + 8);
            else       P[2] = make_uint4(0u, 0u, 0u, 0u);

            float4 t0 = z, t1 = z, t2 = z;
#pragma unroll
            for (int j = 0; j < 3; j++) {
                const __half2* hp = (const __half2*)&P[j];
                const float2 a01 = __half22float2(hp[0]);
                const float2 a23 = __half22float2(hp[1]);
                const float2 b01 = __half22float2(hp[2]);
                const float2 b23 = __half22float2(hp[3]);
                const float4 A = make_float4(a01.x, a01.y, a23.x, a23.y);
                const float4 B = make_float4(b01.x, b01.y, b23.x, b23.y);
#pragma unroll
                for (int dj = 0; dj < 3; dj++) {
                    const float e = we[dj][j], od = wo[dj][j];
                    float4& t = (dj == 0) ? t0 : (dj == 1) ? t1 : t2;
                    t.x += A.x * e + B.x * od;
                    t.y += A.y * e + B.y * od;
                    t.z += A.z * e + B.z * od;
                    t.w += A.w * e + B.w * od;
                }
            }
#pragma unroll
            for (int di = 0; di < 3; di++) {
                const float g = wy[di][r];
#pragma unroll
                for (int dj = 0; dj < 3; dj++) {
                    const float4& t = (dj == 0) ? t0 : (dj == 1) ? t1 : t2;
                    o[di*3+dj].x += t.x * g;
                    o[di*3+dj].y += t.y * g;
                    o[di*3+dj].z += t.z * g;
                    o[di*3+dj].w += t.w * g;
                }
            }
        }

        // ---- 9 race-free scatter phases ----
#pragma unroll
        for (int di = 0; di < 3; di++) {
            const int row = ur - di;
#pragma unroll
            for (int dj = 0; dj < 3; dj++) {
                const int col = uc - dj;
                const bool wr = has && ((unsigned)row < (unsigned)TILE)
                                    && ((unsigned)col < (unsigned)TILE);
                if (wr) {
                    const int idx = row * TILE + col;
                    float4 v = acc[cg][idx];
                    v.x += o[di*3+dj].x; v.y += o[di*3+dj].y;
                    v.z += o[di*3+dj].z; v.w += o[di*3+dj].w;
                    acc[cg][idx] = v;
                }
                __syncthreads();
            }
        }
    }

    // ---------- writeback ----------
    const int ph = tid >> 4, pw = tid & 15;
    const int gidx = (h0 + ph) * W + (w0 + pw);
    const float inv9 = 1.0f / 9.0f;
#pragma unroll
    for (int k = 0; k < 4; k++) {
        const float4 a = acc[k][tid];
        out[(4*k + 0) * HW + gidx] = a.x * inv9;
        out[(4*k + 1) * HW + gidx] = a.y * inv9;
        out[(4*k + 2) * HW + gidx] = a.z * inv9;
        out[(4*k + 3) * HW + gidx] = a.w * inv9;
    }
}

extern "C" void kernel_launch(void* const* d_in, const int* in_sizes, int n_in,
                              void* d_out, int out_size)
{
    const float* img  = (const float*)d_in[0];
    const float* offx = (const float*)d_in[1];
    const float* offy = (const float*)d_in[2];
    float* out = (float*)d_out;

    transpose_kernel<<<HW / TP_PIX, 256>>>(img);

    dim3 grid(W / TILE, H / TILE);
    recon_scatter<<<grid, 256>>>(offx, offy, out);
}

// round 7
// speedup vs baseline: 1.1396x; 1.1396x over previous
#include <cuda_runtime.h>
#include <cuda_fp16.h>

#define W 960
#define H 512
#define C 16
#define HW (H * W)
#define WP (W / 2)           /* 480 pixel-pairs per image row */

// pair-packed fp16 image: uint4 index = pairIdx*4 + cg,
// payload = 8 halves: [pixEven ch0..3, pixOdd ch0..3]
__device__ uint4 g_h4[HW * 2];

__device__ __forceinline__ unsigned h2u_bcast(float w) {
    __half2 h = __float2half2_rn(w);
    return *reinterpret_cast<unsigned*>(&h);
}
__device__ __forceinline__ __half2 u2h(unsigned v) {
    return *reinterpret_cast<__half2*>(&v);
}

// ---------------- transpose+pack CHW fp32 -> pair-packed fp16 ----------------
#define TP_PIX 128
__global__ __launch_bounds__(256) void transpose_kernel(const float* __restrict__ img)
{
    __shared__ float tile[TP_PIX][C + 1];
    const int pix0 = blockIdx.x * TP_PIX;

#pragma unroll
    for (int i = 0; i < 2; i++) {
        const int idx = threadIdx.x + i * 256;
        const int c = idx >> 5;
        const int v = idx & 31;
        const float4 d = *(const float4*)(img + c * HW + pix0 + v * 4);
        tile[v * 4 + 0][c] = d.x;
        tile[v * 4 + 1][c] = d.y;
        tile[v * 4 + 2][c] = d.z;
        tile[v * 4 + 3][c] = d.w;
    }
    __syncthreads();

    {
        const int p2l = threadIdx.x >> 2;
        const int cg  = threadIdx.x & 3;
        const float* re = tile[p2l * 2 + 0];
        const float* ro = tile[p2l * 2 + 1];
        __half2 e01 = __floats2half2_rn(re[cg*4+0], re[cg*4+1]);
        __half2 e23 = __floats2half2_rn(re[cg*4+2], re[cg*4+3]);
        __half2 o01 = __floats2half2_rn(ro[cg*4+0], ro[cg*4+1]);
        __half2 o23 = __floats2half2_rn(ro[cg*4+2], ro[cg*4+3]);
        uint4 v;
        v.x = *reinterpret_cast<unsigned*>(&e01);
        v.y = *reinterpret_cast<unsigned*>(&e23);
        v.z = *reinterpret_cast<unsigned*>(&o01);
        v.w = *reinterpret_cast<unsigned*>(&o23);
        g_h4[((pix0 >> 1) + p2l) * 4 + cg] = v;
    }
}

// ---------------- scatter-patch reconstruct ----------------
#define TILE 16
#define HALO 18
#define NUNIT (HALO * HALO)   /* 324 */
#define NWAVE 6
#define ACC_PITCH 257
#define UPS 9                 /* float4 slots per unit (144B stride) */

__global__ __launch_bounds__(256, 3) void recon_scatter(
    const float* __restrict__ offx,
    const float* __restrict__ offy,
    float* __restrict__ out)
{
    __shared__ float4 acc[4][ACC_PITCH];
    __shared__ uint4 up[NUNIT * UPS];
    unsigned* upw = (unsigned*)up;

    const int tid = threadIdx.x;
    const int h0 = blockIdx.y * TILE;
    const int w0 = blockIdx.x * TILE;

    for (int i = tid; i < 4 * ACC_PITCH; i += 256)
        ((float4*)acc)[i] = make_float4(0.f, 0.f, 0.f, 0.f);

    // ---------- phase A: per-unit params (half2-packed weights) ----------
    // words: [0..8] we2[dj*3+j], [9..17] wo2[dj*3+j], [18..29] wy2[di*4+r],
    //        [30] baseq, [31] need3
    for (int u = tid; u < NUNIT; u += 256) {
        const int ur = u / HALO, uc = u % HALO;
        const int hh = h0 - 1 + ur, ww = w0 - 1 + uc;
        unsigned ub[32];
#pragma unroll
        for (int k = 0; k < 32; k++) ub[k] = 0u;

        if (hh >= 0 && hh < H && ww >= 0 && ww < W) {
            const float sx = __ldg(offx + hh * W + ww);
            const float sy = __ldg(offy + hh * W + ww);

            // ---- x ----
            int x0a[3]; float fxa[3], ma[3]; int pmin = W;
#pragma unroll
            for (int dj = 0; dj < 3; dj++) {
                const int wt = ww + 1 - dj;
                float m = (wt >= 0 && wt < W) ? 1.f : 0.f;
                if (ww == 1     && wt == 0    ) m += 1.f;
                if (ww == W - 2 && wt == W - 1) m += 1.f;
                float cx  = fminf(fmaxf((float)wt - sx, 0.f), (float)(W - 1));
                float ix  = cx * ((float)(W - 1) / (float)W);
                float x0f = floorf(ix);
                x0a[dj] = (int)x0f; fxa[dj] = ix - x0f; ma[dj] = m;
                if (m != 0.f) pmin = min(pmin, x0a[dj]);
            }
            const int px2 = min(pmin & ~1, W - 6);
            int lmax = 0;
#pragma unroll
            for (int dj = 0; dj < 3; dj++) {
                const int l = min(max(x0a[dj] - px2, 0), 4);
                if (ma[dj] != 0.f) lmax = max(lmax, l);
                float v[6];
#pragma unroll
                for (int c = 0; c < 6; c++)
                    v[c] = ma[dj] * ((c == l) ? (1.f - fxa[dj])
                                   : ((c == l + 1) ? fxa[dj] : 0.f));
#pragma unroll
                for (int j = 0; j < 3; j++) {
                    ub[dj * 3 + j]     = h2u_bcast(v[2 * j]);      // even-pixel
                    ub[9 + dj * 3 + j] = h2u_bcast(v[2 * j + 1]);  // odd-pixel
                }
            }

            // ---- y ----
            int y0a[3]; float fya[3], mya[3]; int qmin = H;
#pragma unroll
            for (int di = 0; di < 3; di++) {
                const int ht = hh + 1 - di;
                float m = (ht >= 0 && ht < H) ? 1.f : 0.f;
                if (hh == 1     && ht == 0    ) m += 1.f;
                if (hh == H - 2 && ht == H - 1) m += 1.f;
                float cy  = fminf(fmaxf((float)ht - sy, 0.f), (float)(H - 1));
                float iy  = cy * ((float)(H - 1) / (float)H);
                float y0f = floorf(iy);
                y0a[di] = (int)y0f; fya[di] = iy - y0f; mya[di] = m;
                if (m != 0.f) qmin = min(qmin, y0a[di]);
            }
            const int py = min(qmin, H - 4);
#pragma unroll
            for (int di = 0; di < 3; di++) {
                const int l = min(max(y0a[di] - py, 0), 2);
#pragma unroll
                for (int r = 0; r < 4; r++)
                    ub[18 + di * 4 + r] = h2u_bcast(
                        mya[di] * ((r == l) ? (1.f - fya[di])
                                 : ((r == l + 1) ? fya[di] : 0.f)));
            }
            ub[30] = (unsigned)(py * WP + (px2 >> 1));
            ub[31] = (lmax >= 3) ? 1u : 0u;
        }
#pragma unroll
        for (int k = 0; k < 32; k++) upw[u * (UPS * 4) + k] = ub[k];
    }
    __syncthreads();

    // ---------- phase B: all-half2 math ----------
    const int cg = tid & 3;

    for (int wave = 0; wave < NWAVE; wave++) {
        const int u = wave * 64 + (tid >> 2);
        const bool has = (u < NUNIT);
        const int uu = has ? u : 0;

        const uint4 q0 = up[uu * UPS + 0];
        const uint4 q1 = up[uu * UPS + 1];
        const uint4 q2 = up[uu * UPS + 2];
        const uint4 q3 = up[uu * UPS + 3];
        const uint4 q4 = up[uu * UPS + 4];
        const uint4 q5 = up[uu * UPS + 5];
        const uint4 q6 = up[uu * UPS + 6];
        const uint4 q7 = up[uu * UPS + 7];

        const unsigned we[9] = {q0.x, q0.y, q0.z, q0.w, q1.x, q1.y, q1.z, q1.w, q2.x};
        const unsigned wo[9] = {q2.y, q2.z, q2.w, q3.x, q3.y, q3.z, q3.w, q4.x, q4.y};
        const unsigned wy[12] = {q4.z, q4.w, q5.x, q5.y, q5.z, q5.w,
                                 q6.x, q6.y, q6.z, q6.w, q7.x, q7.y};
        const int baseq = (int)q7.z;
        const bool need3 = (q7.w != 0u);
        const int ur = uu / HALO, uc = uu % HALO;

        const __half2 hz = __float2half2_rn(0.f);
        __half2 o01[9], o23[9];
#pragma unroll
        for (int p = 0; p < 9; p++) { o01[p] = hz; o23[p] = hz; }

#pragma unroll
        for (int r = 0; r < 4; r++) {
            const int qb = (baseq + r * WP) * 4 + cg;
            const uint4 P0 = __ldg(g_h4 + qb);
            const uint4 P1 = __ldg(g_h4 + qb + 4);
            const uint4 P2 = need3 ? __ldg(g_h4 + qb + 8) : make_uint4(0u, 0u, 0u, 0u);

            const __half2 A01[3] = {u2h(P0.x), u2h(P1.x), u2h(P2.x)};
            const __half2 A23[3] = {u2h(P0.y), u2h(P1.y), u2h(P2.y)};
            const __half2 B01[3] = {u2h(P0.z), u2h(P1.z), u2h(P2.z)};
            const __half2 B23[3] = {u2h(P0.w), u2h(P1.w), u2h(P2.w)};

#pragma unroll
            for (int dj = 0; dj < 3; dj++) {
                __half2 t01 = __hmul2(A01[0], u2h(we[dj*3+0]));
                __half2 t23 = __hmul2(A23[0], u2h(we[dj*3+0]));
                t01 = __hfma2(B01[0], u2h(wo[dj*3+0]), t01);
                t23 = __hfma2(B23[0], u2h(wo[dj*3+0]), t23);
                t01 = __hfma2(A01[1], u2h(we[dj*3+1]), t01);
                t23 = __hfma2(A23[1], u2h(we[dj*3+1]), t23);
                t01 = __hfma2(B01[1], u2h(wo[dj*3+1]), t01);
                t23 = __hfma2(B23[1], u2h(wo[dj*3+1]), t23);
                t01 = __hfma2(A01[2], u2h(we[dj*3+2]), t01);
                t23 = __hfma2(A23[2], u2h(we[dj*3+2]), t23);
                t01 = __hfma2(B01[2], u2h(wo[dj*3+2]), t01);
                t23 = __hfma2(B23[2], u2h(wo[dj*3+2]), t23);
#pragma unroll
                for (int di = 0; di < 3; di++) {
                    const __half2 g = u2h(wy[di*4 + r]);
                    o01[di*3+dj] = __hfma2(t01, g, o01[di*3+dj]);
                    o23[di*3+dj] = __hfma2(t23, g, o23[di*3+dj]);
                }
            }
        }

        // ---- 9 race-free scatter phases (convert to fp32 here) ----
#pragma unroll
        for (int di = 0; di < 3; di++) {
            const int row = ur - di;
#pragma unroll
            for (int dj = 0; dj < 3; dj++) {
                const int col = uc - dj;
                const bool wr = has && ((unsigned)row < (unsigned)TILE)
                                    && ((unsigned)col < (unsigned)TILE);
                if (wr) {
                    const int idx = row * TILE + col;
                    const float2 lo = __half22float2(o01[di*3+dj]);
                    const float2 hi = __half22float2(o23[di*3+dj]);
                    float4 v = acc[cg][idx];
                    v.x += lo.x; v.y += lo.y;
                    v.z += hi.x; v.w += hi.y;
                    acc[cg][idx] = v;
                }
                __syncthreads();
            }
        }
    }

    // ---------- writeback ----------
    const int ph = tid >> 4, pw = tid & 15;
    const int gidx = (h0 + ph) * W + (w0 + pw);
    const float inv9 = 1.0f / 9.0f;
#pragma unroll
    for (int k = 0; k < 4; k++) {
        const float4 a = acc[k][tid];
        out[(4*k + 0) * HW + gidx] = a.x * inv9;
        out[(4*k + 1) * HW + gidx] = a.y * inv9;
        out[(4*k + 2) * HW + gidx] = a.z * inv9;
        out[(4*k + 3) * HW + gidx] = a.w * inv9;
    }
}

extern "C" void kernel_launch(void* const* d_in, const int* in_sizes, int n_in,
                              void* d_out, int out_size)
{
    const float* img  = (const float*)d_in[0];
    const float* offx = (const float*)d_in[1];
    const float* offy = (const float*)d_in[2];
    float* out = (float*)d_out;

    transpose_kernel<<<HW / TP_PIX, 256>>>(img);

    dim3 grid(W / TILE, H / TILE);
    recon_scatter<<<grid, 256>>>(offx, offy, out);
}

// round 8
// speedup vs baseline: 1.3070x; 1.1468x over previous
#include <cuda_runtime.h>
#include <cuda_fp16.h>

#define W 960
#define H 512
#define C 16
#define HW (H * W)
#define WP (W / 2)

// pair-packed fp16 image: uint4 index = pairIdx*4 + cg,
// payload = 8 halves: [pixEven ch0..3, pixOdd ch0..3]
__device__ uint4 g_h4[HW * 2];

__device__ __forceinline__ unsigned h2pack(float a, float b) {
    __half2 h = __floats2half2_rn(a, b);
    return *reinterpret_cast<unsigned*>(&h);
}
__device__ __forceinline__ __half2 u2h(unsigned v) {
    return *reinterpret_cast<__half2*>(&v);
}

// ---------------- transpose+pack CHW fp32 -> pair-packed fp16 ----------------
#define TP_PIX 128
__global__ __launch_bounds__(256) void transpose_kernel(const float* __restrict__ img)
{
    __shared__ float tile[TP_PIX][C + 1];
    const int pix0 = blockIdx.x * TP_PIX;

#pragma unroll
    for (int i = 0; i < 2; i++) {
        const int idx = threadIdx.x + i * 256;
        const int c = idx >> 5;
        const int v = idx & 31;
        const float4 d = *(const float4*)(img + c * HW + pix0 + v * 4);
        tile[v * 4 + 0][c] = d.x;
        tile[v * 4 + 1][c] = d.y;
        tile[v * 4 + 2][c] = d.z;
        tile[v * 4 + 3][c] = d.w;
    }
    __syncthreads();

    {
        const int p2l = threadIdx.x >> 2;
        const int cg  = threadIdx.x & 3;
        const float* re = tile[p2l * 2 + 0];
        const float* ro = tile[p2l * 2 + 1];
        uint4 v;
        v.x = h2pack(re[cg*4+0], re[cg*4+1]);
        v.y = h2pack(re[cg*4+2], re[cg*4+3]);
        v.z = h2pack(ro[cg*4+0], ro[cg*4+1]);
        v.w = h2pack(ro[cg*4+2], ro[cg*4+3]);
        g_h4[((pix0 >> 1) + p2l) * 4 + cg] = v;
    }
}

// ---------------- scatter-patch reconstruct ----------------
#define TILE 16
#define HALO 18
#define NUNIT (HALO * HALO)   /* 324 */
#define NWAVE 6
#define ACC_PITCH 257
#define UPW 20                /* words per unit (80B stride, conflict-free) */

__global__ __launch_bounds__(256, 4) void recon_scatter(
    const float* __restrict__ offx,
    const float* __restrict__ offy,
    float* __restrict__ out)
{
    __shared__ float4 acc[4][ACC_PITCH];
    __shared__ unsigned upw[NUNIT * UPW];

    const int tid = threadIdx.x;
    const int h0 = blockIdx.y * TILE;
    const int w0 = blockIdx.x * TILE;

    for (int i = tid; i < 4 * ACC_PITCH; i += 256)
        ((float4*)acc)[i] = make_float4(0.f, 0.f, 0.f, 0.f);

    // ---------- phase A: per-unit params (half2 pair-packed) ----------
    // words: [0..8]  wexo[k]   = half2(we_k, wo_k), k = dj*3+j
    //        [9..11] wy01[di]  = half2(wy[di][0], wy[di][1])
    //        [12..14] wy23[di] = half2(wy[di][2], wy[di][3])
    //        [15] baseq   [16] need3
    for (int u = tid; u < NUNIT; u += 256) {
        const int ur = u / HALO, uc = u % HALO;
        const int hh = h0 - 1 + ur, ww = w0 - 1 + uc;
        unsigned ub[17];
#pragma unroll
        for (int k = 0; k < 17; k++) ub[k] = 0u;

        if (hh >= 0 && hh < H && ww >= 0 && ww < W) {
            const float sx = __ldg(offx + hh * W + ww);
            const float sy = __ldg(offy + hh * W + ww);

            // ---- x ----
            int x0a[3]; float fxa[3], ma[3]; int pmin = W;
#pragma unroll
            for (int dj = 0; dj < 3; dj++) {
                const int wt = ww + 1 - dj;
                float m = (wt >= 0 && wt < W) ? 1.f : 0.f;
                if (ww == 1     && wt == 0    ) m += 1.f;
                if (ww == W - 2 && wt == W - 1) m += 1.f;
                float cx  = fminf(fmaxf((float)wt - sx, 0.f), (float)(W - 1));
                float ix  = cx * ((float)(W - 1) / (float)W);
                float x0f = floorf(ix);
                x0a[dj] = (int)x0f; fxa[dj] = ix - x0f; ma[dj] = m;
                if (m != 0.f) pmin = min(pmin, x0a[dj]);
            }
            const int px2 = min(pmin & ~1, W - 6);
            int lmax = 0;
#pragma unroll
            for (int dj = 0; dj < 3; dj++) {
                const int l = min(max(x0a[dj] - px2, 0), 4);
                if (ma[dj] != 0.f) lmax = max(lmax, l);
                float v[6];
#pragma unroll
                for (int c = 0; c < 6; c++)
                    v[c] = ma[dj] * ((c == l) ? (1.f - fxa[dj])
                                   : ((c == l + 1) ? fxa[dj] : 0.f));
#pragma unroll
                for (int j = 0; j < 3; j++)
                    ub[dj * 3 + j] = h2pack(v[2 * j], v[2 * j + 1]);
            }

            // ---- y ----
            int y0a[3]; float fya[3], mya[3]; int qmin = H;
#pragma unroll
            for (int di = 0; di < 3; di++) {
                const int ht = hh + 1 - di;
                float m = (ht >= 0 && ht < H) ? 1.f : 0.f;
                if (hh == 1     && ht == 0    ) m += 1.f;
                if (hh == H - 2 && ht == H - 1) m += 1.f;
                float cy  = fminf(fmaxf((float)ht - sy, 0.f), (float)(H - 1));
                float iy  = cy * ((float)(H - 1) / (float)H);
                float y0f = floorf(iy);
                y0a[di] = (int)y0f; fya[di] = iy - y0f; mya[di] = m;
                if (m != 0.f) qmin = min(qmin, y0a[di]);
            }
            const int py = min(qmin, H - 4);
#pragma unroll
            for (int di = 0; di < 3; di++) {
                const int l = min(max(y0a[di] - py, 0), 2);
                float g[4];
#pragma unroll
                for (int r = 0; r < 4; r++)
                    g[r] = mya[di] * ((r == l) ? (1.f - fya[di])
                                    : ((r == l + 1) ? fya[di] : 0.f));
                ub[9 + di]  = h2pack(g[0], g[1]);
                ub[12 + di] = h2pack(g[2], g[3]);
            }
            ub[15] = (unsigned)(py * WP + (px2 >> 1));
            ub[16] = (lmax >= 3) ? 1u : 0u;
        }
        // 5 uint4 stores (stride 80B)
        uint4* dst = (uint4*)(upw + u * UPW);
        dst[0] = make_uint4(ub[0],  ub[1],  ub[2],  ub[3]);
        dst[1] = make_uint4(ub[4],  ub[5],  ub[6],  ub[7]);
        dst[2] = make_uint4(ub[8],  ub[9],  ub[10], ub[11]);
        dst[3] = make_uint4(ub[12], ub[13], ub[14], ub[15]);
        dst[4] = make_uint4(ub[16], 0u, 0u, 0u);
    }
    __syncthreads();

    // ---------- phase B ----------
    const int cg = tid & 3;

    for (int wave = 0; wave < NWAVE; wave++) {
        const int u = wave * 64 + (tid >> 2);
        const bool has = (u < NUNIT);
        const int uu = has ? u : 0;

        const uint4* src = (const uint4*)(upw + uu * UPW);
        const uint4 q0 = src[0];
        const uint4 q1 = src[1];
        const uint4 q2 = src[2];
        const uint4 q3 = src[3];
        const uint4 q4 = src[4];

        const unsigned wexo[9] = {q0.x, q0.y, q0.z, q0.w,
                                  q1.x, q1.y, q1.z, q1.w, q2.x};
        const unsigned wy01v[3] = {q2.y, q2.z, q2.w};
        const unsigned wy23v[3] = {q3.x, q3.y, q3.z};
        const int baseq = (int)q3.w;
        const bool need3 = (q4.x != 0u);
        const int ur = uu / HALO, uc = uu % HALO;

        const __half2 hz = __float2half2_rn(0.f);
        __half2 o01[9], o23[9];
#pragma unroll
        for (int p = 0; p < 9; p++) { o01[p] = hz; o23[p] = hz; }

#pragma unroll
        for (int r = 0; r < 4; r++) {
            const int qb = (baseq + r * WP) * 4 + cg;
            const uint4 P0 = __ldg(g_h4 + qb);
            const uint4 P1 = __ldg(g_h4 + qb + 4);
            const uint4 P2 = need3 ? __ldg(g_h4 + qb + 8) : make_uint4(0u, 0u, 0u, 0u);

            const __half2 A01[3] = {u2h(P0.x), u2h(P1.x), u2h(P2.x)};
            const __half2 A23[3] = {u2h(P0.y), u2h(P1.y), u2h(P2.y)};
            const __half2 B01[3] = {u2h(P0.z), u2h(P1.z), u2h(P2.z)};
            const __half2 B23[3] = {u2h(P0.w), u2h(P1.w), u2h(P2.w)};

#pragma unroll
            for (int dj = 0; dj < 3; dj++) {
                const __half2 w0e = __low2half2 (u2h(wexo[dj*3+0]));
                const __half2 w0o = __high2half2(u2h(wexo[dj*3+0]));
                const __half2 w1e = __low2half2 (u2h(wexo[dj*3+1]));
                const __half2 w1o = __high2half2(u2h(wexo[dj*3+1]));
                const __half2 w2e = __low2half2 (u2h(wexo[dj*3+2]));
                const __half2 w2o = __high2half2(u2h(wexo[dj*3+2]));

                __half2 t01 = __hmul2(A01[0], w0e);
                __half2 t23 = __hmul2(A23[0], w0e);
                t01 = __hfma2(B01[0], w0o, t01);
                t23 = __hfma2(B23[0], w0o, t23);
                t01 = __hfma2(A01[1], w1e, t01);
                t23 = __hfma2(A23[1], w1e, t23);
                t01 = __hfma2(B01[1], w1o, t01);
                t23 = __hfma2(B23[1], w1o, t23);
                t01 = __hfma2(A01[2], w2e, t01);
                t23 = __hfma2(A23[2], w2e, t23);
                t01 = __hfma2(B01[2], w2o, t01);
                t23 = __hfma2(B23[2], w2o, t23);
#pragma unroll
                for (int di = 0; di < 3; di++) {
                    const unsigned wsel = (r < 2) ? wy01v[di] : wy23v[di];
                    const __half2 g = ((r & 1) == 0) ? __low2half2(u2h(wsel))
                                                     : __high2half2(u2h(wsel));
                    o01[di*3+dj] = __hfma2(t01, g, o01[di*3+dj]);
                    o23[di*3+dj] = __hfma2(t23, g, o23[di*3+dj]);
                }
            }
        }

        // ---- 9 race-free scatter phases ----
#pragma unroll
        for (int di = 0; di < 3; di++) {
            const int row = ur - di;
#pragma unroll
            for (int dj = 0; dj < 3; dj++) {
                const int col = uc - dj;
                const bool wr = has && ((unsigned)row < (unsigned)TILE)
                                    && ((unsigned)col < (unsigned)TILE);
                if (wr) {
                    const int idx = row * TILE + col;
                    const float2 lo = __half22float2(o01[di*3+dj]);
                    const float2 hi = __half22float2(o23[di*3+dj]);
                    float4 v = acc[cg][idx];
                    v.x += lo.x; v.y += lo.y;
                    v.z += hi.x; v.w += hi.y;
                    acc[cg][idx] = v;
                }
                __syncthreads();
            }
        }
    }

    // ---------- writeback ----------
    const int ph = tid >> 4, pw = tid & 15;
    const int gidx = (h0 + ph) * W + (w0 + pw);
    const float inv9 = 1.0f / 9.0f;
#pragma unroll
    for (int k = 0; k < 4; k++) {
        const float4 a = acc[k][tid];
        out[(4*k + 0) * HW + gidx] = a.x * inv9;
        out[(4*k + 1) * HW + gidx] = a.y * inv9;
        out[(4*k + 2) * HW + gidx] = a.z * inv9;
        out[(4*k + 3) * HW + gidx] = a.w * inv9;
    }
}

extern "C" void kernel_launch(void* const* d_in, const int* in_sizes, int n_in,
                              void* d_out, int out_size)
{
    const float* img  = (const float*)d_in[0];
    const float* offx = (const float*)d_in[1];
    const float* offy = (const float*)d_in[2];
    float* out = (float*)d_out;

    transpose_kernel<<<HW / TP_PIX, 256>>>(img);

    dim3 grid(W / TILE, H / TILE);
    recon_scatter<<<grid, 256>>>(offx, offy, out);
}

// round 9
// speedup vs baseline: 1.3719x; 1.0497x over previous
#include <cuda_runtime.h>
#include <cuda_fp16.h>

#define W 960
#define H 512
#define C 16
#define HW (H * W)
#define WP (W / 2)

// pair-packed fp16 image: uint4 index = pairIdx*4 + cg,
// payload = 8 halves: [pixEven ch0..3, pixOdd ch0..3]
__device__ uint4 g_h4[HW * 2];

__device__ __forceinline__ unsigned h2pack(float a, float b) {
    __half2 h = __floats2half2_rn(a, b);
    return *reinterpret_cast<unsigned*>(&h);
}
__device__ __forceinline__ __half2 u2h(unsigned v) {
    return *reinterpret_cast<__half2*>(&v);
}
__device__ __forceinline__ unsigned h2u(__half2 h) {
    return *reinterpret_cast<unsigned*>(&h);
}

// ---------------- transpose+pack CHW fp32 -> pair-packed fp16 ----------------
#define TP_PIX 128
__global__ __launch_bounds__(256) void transpose_kernel(const float* __restrict__ img)
{
    __shared__ float tile[TP_PIX][C + 1];
    const int pix0 = blockIdx.x * TP_PIX;

#pragma unroll
    for (int i = 0; i < 2; i++) {
        const int idx = threadIdx.x + i * 256;
        const int c = idx >> 5;
        const int v = idx & 31;
        const float4 d = *(const float4*)(img + c * HW + pix0 + v * 4);
        tile[v * 4 + 0][c] = d.x;
        tile[v * 4 + 1][c] = d.y;
        tile[v * 4 + 2][c] = d.z;
        tile[v * 4 + 3][c] = d.w;
    }
    __syncthreads();

    {
        const int p2l = threadIdx.x >> 2;
        const int cg  = threadIdx.x & 3;
        const float* re = tile[p2l * 2 + 0];
        const float* ro = tile[p2l * 2 + 1];
        uint4 v;
        v.x = h2pack(re[cg*4+0], re[cg*4+1]);
        v.y = h2pack(re[cg*4+2], re[cg*4+3]);
        v.z = h2pack(ro[cg*4+0], ro[cg*4+1]);
        v.w = h2pack(ro[cg*4+2], ro[cg*4+3]);
        g_h4[((pix0 >> 1) + p2l) * 4 + cg] = v;
    }
}

// ---------------- scatter-patch reconstruct ----------------
#define TILE 16
#define HALO 18
#define NUNIT (HALO * HALO)   /* 324 */
#define NUPAD 384             /* padded (zero-filled) param slots */
#define NWAVE 6
#define ACC_PITCH 257
#define UPW 20                /* words per unit (80B stride, conflict-free) */

__global__ __launch_bounds__(256, 4) void recon_scatter(
    const float* __restrict__ offx,
    const float* __restrict__ offy,
    float* __restrict__ out)
{
    __shared__ float4 acc[4][ACC_PITCH];
    __shared__ unsigned upw[NUPAD * UPW];

    const int tid = threadIdx.x;
    const int h0 = blockIdx.y * TILE;
    const int w0 = blockIdx.x * TILE;

    for (int i = tid; i < 4 * ACC_PITCH; i += 256)
        ((float4*)acc)[i] = make_float4(0.f, 0.f, 0.f, 0.f);

    // ---------- phase A: per-unit params (zero-padded to NUPAD) ----------
    for (int u = tid; u < NUPAD; u += 256) {
        const int ur = u / HALO, uc = u % HALO;
        const int hh = h0 - 1 + ur, ww = w0 - 1 + uc;
        unsigned ub[17];
#pragma unroll
        for (int k = 0; k < 17; k++) ub[k] = 0u;

        if (u < NUNIT && hh >= 0 && hh < H && ww >= 0 && ww < W) {
            const float sx = __ldg(offx + hh * W + ww);
            const float sy = __ldg(offy + hh * W + ww);

            // ---- x ----
            int x0a[3]; float fxa[3], ma[3]; int pmin = W;
#pragma unroll
            for (int dj = 0; dj < 3; dj++) {
                const int wt = ww + 1 - dj;
                float m = (wt >= 0 && wt < W) ? 1.f : 0.f;
                if (ww == 1     && wt == 0    ) m += 1.f;
                if (ww == W - 2 && wt == W - 1) m += 1.f;
                float cx  = fminf(fmaxf((float)wt - sx, 0.f), (float)(W - 1));
                float ix  = cx * ((float)(W - 1) / (float)W);
                float x0f = floorf(ix);
                x0a[dj] = (int)x0f; fxa[dj] = ix - x0f; ma[dj] = m;
                if (m != 0.f) pmin = min(pmin, x0a[dj]);
            }
            const int px2 = min(pmin & ~1, W - 6);
            int lmax = 0;
#pragma unroll
            for (int dj = 0; dj < 3; dj++) {
                const int l = min(max(x0a[dj] - px2, 0), 4);
                if (ma[dj] != 0.f) lmax = max(lmax, l);
                float v[6];
#pragma unroll
                for (int c = 0; c < 6; c++)
                    v[c] = ma[dj] * ((c == l) ? (1.f - fxa[dj])
                                   : ((c == l + 1) ? fxa[dj] : 0.f));
#pragma unroll
                for (int j = 0; j < 3; j++)
                    ub[dj * 3 + j] = h2pack(v[2 * j], v[2 * j + 1]);
            }

            // ---- y ----
            int y0a[3]; float fya[3], mya[3]; int qmin = H;
#pragma unroll
            for (int di = 0; di < 3; di++) {
                const int ht = hh + 1 - di;
                float m = (ht >= 0 && ht < H) ? 1.f : 0.f;
                if (hh == 1     && ht == 0    ) m += 1.f;
                if (hh == H - 2 && ht == H - 1) m += 1.f;
                float cy  = fminf(fmaxf((float)ht - sy, 0.f), (float)(H - 1));
                float iy  = cy * ((float)(H - 1) / (float)H);
                float y0f = floorf(iy);
                y0a[di] = (int)y0f; fya[di] = iy - y0f; mya[di] = m;
                if (m != 0.f) qmin = min(qmin, y0a[di]);
            }
            const int py = min(qmin, H - 4);
#pragma unroll
            for (int di = 0; di < 3; di++) {
                const int l = min(max(y0a[di] - py, 0), 2);
                float g[4];
#pragma unroll
                for (int r = 0; r < 4; r++)
                    g[r] = mya[di] * ((r == l) ? (1.f - fya[di])
                                    : ((r == l + 1) ? fya[di] : 0.f));
                ub[9 + di]  = h2pack(g[0], g[1]);
                ub[12 + di] = h2pack(g[2], g[3]);
            }
            ub[15] = (unsigned)(py * WP + (px2 >> 1));
            ub[16] = (lmax >= 3) ? 1u : 0u;
        }
        uint4* dst = (uint4*)(upw + u * UPW);
        dst[0] = make_uint4(ub[0],  ub[1],  ub[2],  ub[3]);
        dst[1] = make_uint4(ub[4],  ub[5],  ub[6],  ub[7]);
        dst[2] = make_uint4(ub[8],  ub[9],  ub[10], ub[11]);
        dst[3] = make_uint4(ub[12], ub[13], ub[14], ub[15]);
        dst[4] = make_uint4(ub[16], 0u, 0u, 0u);
    }
    __syncthreads();

    // ---------- phase B ----------
    const int cg = tid & 3;
    const int k  = (tid & 31) >> 2;   // unit index within warp (0..7)

    for (int wave = 0; wave < NWAVE; wave++) {
        const int u = wave * 64 + (tid >> 2);   // < NUPAD always

        const uint4* src = (const uint4*)(upw + u * UPW);
        const uint4 q0 = src[0];
        const uint4 q1 = src[1];
        const uint4 q2 = src[2];
        const uint4 q3 = src[3];
        const uint4 q4 = src[4];

        const unsigned wexo[9] = {q0.x, q0.y, q0.z, q0.w,
                                  q1.x, q1.y, q1.z, q1.w, q2.x};
        const unsigned wy01v[3] = {q2.y, q2.z, q2.w};
        const unsigned wy23v[3] = {q3.x, q3.y, q3.z};
        const int baseq = (int)q3.w;
        const bool need3 = (q4.x != 0u);
        const int ur = u / HALO, uc = u % HALO;

        const __half2 hz = __float2half2_rn(0.f);
        __half2 o01[9], o23[9];
#pragma unroll
        for (int p = 0; p < 9; p++) { o01[p] = hz; o23[p] = hz; }

#pragma unroll
        for (int r = 0; r < 4; r++) {
            const int qb = (baseq + r * WP) * 4 + cg;
            const uint4 P0 = __ldg(g_h4 + qb);
            const uint4 P1 = __ldg(g_h4 + qb + 4);
            const uint4 P2 = need3 ? __ldg(g_h4 + qb + 8) : make_uint4(0u, 0u, 0u, 0u);

            const __half2 A01[3] = {u2h(P0.x), u2h(P1.x), u2h(P2.x)};
            const __half2 A23[3] = {u2h(P0.y), u2h(P1.y), u2h(P2.y)};
            const __half2 B01[3] = {u2h(P0.z), u2h(P1.z), u2h(P2.z)};
            const __half2 B23[3] = {u2h(P0.w), u2h(P1.w), u2h(P2.w)};

#pragma unroll
            for (int dj = 0; dj < 3; dj++) {
                const __half2 w0e = __low2half2 (u2h(wexo[dj*3+0]));
                const __half2 w0o = __high2half2(u2h(wexo[dj*3+0]));
                const __half2 w1e = __low2half2 (u2h(wexo[dj*3+1]));
                const __half2 w1o = __high2half2(u2h(wexo[dj*3+1]));
                const __half2 w2e = __low2half2 (u2h(wexo[dj*3+2]));
                const __half2 w2o = __high2half2(u2h(wexo[dj*3+2]));

                __half2 t01 = __hmul2(A01[0], w0e);
                __half2 t23 = __hmul2(A23[0], w0e);
                t01 = __hfma2(B01[0], w0o, t01);
                t23 = __hfma2(B23[0], w0o, t23);
                t01 = __hfma2(A01[1], w1e, t01);
                t23 = __hfma2(A23[1], w1e, t23);
                t01 = __hfma2(B01[1], w1o, t01);
                t23 = __hfma2(B23[1], w1o, t23);
                t01 = __hfma2(A01[2], w2e, t01);
                t23 = __hfma2(A23[2], w2e, t23);
                t01 = __hfma2(B01[2], w2o, t01);
                t23 = __hfma2(B23[2], w2o, t23);
#pragma unroll
                for (int di = 0; di < 3; di++) {
                    const unsigned wsel = (r < 2) ? wy01v[di] : wy23v[di];
                    const __half2 g = ((r & 1) == 0) ? __low2half2(u2h(wsel))
                                                     : __high2half2(u2h(wsel));
                    o01[di*3+dj] = __hfma2(t01, g, o01[di*3+dj]);
                    o23[di*3+dj] = __hfma2(t23, g, o23[di*3+dj]);
                }
            }
        }

        // ---- shuffle-combined scatter: per di, 1 comb phase + 1 leftover phase ----
#pragma unroll
        for (int di = 0; di < 3; di++) {
            const int row = ur - di;

            // comb: cell (row, uc) = o0(k) + o1(k+1) + o2(k+2)
            const unsigned a1 = __shfl_down_sync(0xffffffffu, h2u(o01[di*3+1]), 4);
            const unsigned b1 = __shfl_down_sync(0xffffffffu, h2u(o23[di*3+1]), 4);
            const unsigned a2 = __shfl_down_sync(0xffffffffu, h2u(o01[di*3+2]), 8);
            const unsigned b2 = __shfl_down_sync(0xffffffffu, h2u(o23[di*3+2]), 8);
            __half2 c01 = o01[di*3+0];
            __half2 c23 = o23[di*3+0];
            if (k <= 6) { c01 = __hadd2(c01, u2h(a1)); c23 = __hadd2(c23, u2h(b1)); }
            if (k <= 5) { c01 = __hadd2(c01, u2h(a2)); c23 = __hadd2(c23, u2h(b2)); }
            if ((unsigned)row < (unsigned)TILE && (unsigned)uc < (unsigned)TILE) {
                const int idx = row * TILE + uc;
                const float2 lo = __half22float2(c01);
                const float2 hi = __half22float2(c23);
                float4 v = acc[cg][idx];
                v.x += lo.x; v.y += lo.y; v.z += hi.x; v.w += hi.y;
                acc[cg][idx] = v;
            }
            __syncthreads();

            // leftover (k==0 only): terms whose comb owner is in the previous warp
            const unsigned la = __shfl_down_sync(0xffffffffu, h2u(o01[di*3+2]), 4);
            const unsigned lb = __shfl_down_sync(0xffffffffu, h2u(o23[di*3+2]), 4);
            if (k == 0) {
                // cellA = (row, uc-1): o1(k0) + o2(k1)
                if ((unsigned)row < (unsigned)TILE &&
                    (unsigned)(uc - 1) < (unsigned)TILE) {
                    __half2 A01h = __hadd2(o01[di*3+1], u2h(la));
                    __half2 A23h = __hadd2(o23[di*3+1], u2h(lb));
                    const int idx = row * TILE + (uc - 1);
                    const float2 lo = __half22float2(A01h);
                    const float2 hi = __half22float2(A23h);
                    float4 v = acc[cg][idx];
                    v.x += lo.x; v.y += lo.y; v.z += hi.x; v.w += hi.y;
                    acc[cg][idx] = v;
                }
                // cellB = (row, uc-2): o2(k0)
                if ((unsigned)row < (unsigned)TILE &&
                    (unsigned)(uc - 2) < (unsigned)TILE) {
                    const int idx = row * TILE + (uc - 2);
                    const float2 lo = __half22float2(o01[di*3+2]);
                    const float2 hi = __half22float2(o23[di*3+2]);
                    float4 v = acc[cg][idx];
                    v.x += lo.x; v.y += lo.y; v.z += hi.x; v.w += hi.y;
                    acc[cg][idx] = v;
                }
            }
            __syncthreads();
        }
    }

    // ---------- writeback ----------
    const int ph = tid >> 4, pw = tid & 15;
    const int gidx = (h0 + ph) * W + (w0 + pw);
    const float inv9 = 1.0f / 9.0f;
#pragma unroll
    for (int kk = 0; kk < 4; kk++) {
        const float4 a = acc[kk][tid];
        out[(4*kk + 0) * HW + gidx] = a.x * inv9;
        out[(4*kk + 1) * HW + gidx] = a.y * inv9;
        out[(4*kk + 2) * HW + gidx] = a.z * inv9;
        out[(4*kk + 3) * HW + gidx] = a.w * inv9;
    }
}

extern "C" void kernel_launch(void* const* d_in, const int* in_sizes, int n_in,
                              void* d_out, int out_size)
{
    const float* img  = (const float*)d_in[0];
    const float* offx = (const float*)d_in[1];
    const float* offy = (const float*)d_in[2];
    float* out = (float*)d_out;

    transpose_kernel<<<HW / TP_PIX, 256>>>(img);

    dim3 grid(W / TILE, H / TILE);
    recon_scatter<<<grid, 256>>>(offx, offy, out);
}

// round 11
// speedup vs baseline: 1.4024x; 1.0222x over previous
#include <cuda_runtime.h>
#include <cuda_fp16.h>

#define W 960
#define H 512
#define C 16
#define HW (H * W)
#define WP (W / 2)

// pair-packed fp16 image: uint4 index = pairIdx*4 + cg,
// payload = 8 halves: [pixEven ch0..1, pixEven ch2..3, pixOdd ch0..1, pixOdd ch2..3]
__device__ uint4 g_h4[HW * 2];

__device__ __forceinline__ unsigned h2pack(float a, float b) {
    __half2 h = __floats2half2_rn(a, b);
    return *reinterpret_cast<unsigned*>(&h);
}
__device__ __forceinline__ __half2 u2h(unsigned v) {
    return *reinterpret_cast<__half2*>(&v);
}
__device__ __forceinline__ unsigned h2u(__half2 h) {
    return *reinterpret_cast<unsigned*>(&h);
}

// ---------------- transpose+pack CHW fp32 -> pair-packed fp16 ----------------
#define TP_PIX 128
__global__ __launch_bounds__(256) void transpose_kernel(const float* __restrict__ img)
{
    __shared__ float tile[TP_PIX][C + 1];
    const int pix0 = blockIdx.x * TP_PIX;

#pragma unroll
    for (int i = 0; i < 2; i++) {
        const int idx = threadIdx.x + i * 256;
        const int c = idx >> 5;
        const int v = idx & 31;
        const float4 d = *(const float4*)(img + c * HW + pix0 + v * 4);
        tile[v * 4 + 0][c] = d.x;
        tile[v * 4 + 1][c] = d.y;
        tile[v * 4 + 2][c] = d.z;
        tile[v * 4 + 3][c] = d.w;
    }
    __syncthreads();

    {
        const int p2l = threadIdx.x >> 2;
        const int cg  = threadIdx.x & 3;
        const float* re = tile[p2l * 2 + 0];
        const float* ro = tile[p2l * 2 + 1];
        uint4 v;
        v.x = h2pack(re[cg*4+0], re[cg*4+1]);
        v.y = h2pack(re[cg*4+2], re[cg*4+3]);
        v.z = h2pack(ro[cg*4+0], ro[cg*4+1]);
        v.w = h2pack(ro[cg*4+2], ro[cg*4+3]);
        g_h4[((pix0 >> 1) + p2l) * 4 + cg] = v;
    }
}

// ---------------- scatter-patch reconstruct ----------------
#define TILE 16
#define HALO 18
#define NUNIT (HALO * HALO)   /* 324 */
#define NUPAD 384
#define NWAVE 6
#define ACC_PITCH 257
#define UPW 20                /* words per unit: 80B stride -> 16B-aligned, conflict-free */

__global__ __launch_bounds__(256, 4) void recon_scatter(
    const float* __restrict__ offx,
    const float* __restrict__ offy,
    float* __restrict__ out)
{
    __shared__ float4 acc[4][ACC_PITCH];
    __shared__ unsigned upw[NUPAD * UPW];

    const int tid = threadIdx.x;
    const int h0 = blockIdx.y * TILE;
    const int w0 = blockIdx.x * TILE;

    for (int i = tid; i < 4 * ACC_PITCH; i += 256)
        ((float4*)acc)[i] = make_float4(0.f, 0.f, 0.f, 0.f);

    // ---------- phase A: per-unit params ----------
    // words: [0..5] wx: dj*2 + {lo(w0,w1), hi(w2,w3)}
    //        [6..8] wy01[di], [9..11] wy23[di]
    //        [12]   base word index | parity<<31
    for (int u = tid; u < NUPAD; u += 256) {
        const int ur = u / HALO, uc = u % HALO;
        const int hh = h0 - 1 + ur, ww = w0 - 1 + uc;
        unsigned ub[13];
#pragma unroll
        for (int k = 0; k < 13; k++) ub[k] = 0u;

        if (u < NUNIT && hh >= 0 && hh < H && ww >= 0 && ww < W) {
            const float sx = __ldg(offx + hh * W + ww);
            const float sy = __ldg(offy + hh * W + ww);

            // ---- x: 4-wide unaligned window ----
            int x0a[3]; float fxa[3], ma[3]; int pmin = W;
#pragma unroll
            for (int dj = 0; dj < 3; dj++) {
                const int wt = ww + 1 - dj;
                float m = (wt >= 0 && wt < W) ? 1.f : 0.f;
                if (ww == 1     && wt == 0    ) m += 1.f;
                if (ww == W - 2 && wt == W - 1) m += 1.f;
                float cx  = fminf(fmaxf((float)wt - sx, 0.f), (float)(W - 1));
                float ix  = cx * ((float)(W - 1) / (float)W);
                float x0f = floorf(ix);
                x0a[dj] = (int)x0f; fxa[dj] = ix - x0f; ma[dj] = m;
                if (m != 0.f) pmin = min(pmin, x0a[dj]);
            }
            const int px = min(max(pmin, 0), W - 4);   // window cols px..px+3
            const unsigned parity = (unsigned)(px & 1);
#pragma unroll
            for (int dj = 0; dj < 3; dj++) {
                const int l = min(max(x0a[dj] - px, 0), 2);  // taps at l, l+1 (<=3)
                float v[4];
#pragma unroll
                for (int c = 0; c < 4; c++)
                    v[c] = ma[dj] * ((c == l) ? (1.f - fxa[dj])
                                   : ((c == l + 1) ? fxa[dj] : 0.f));
                ub[dj * 2 + 0] = h2pack(v[0], v[1]);
                ub[dj * 2 + 1] = h2pack(v[2], v[3]);
            }

            // ---- y ----
            int y0a[3]; float fya[3], mya[3]; int qmin = H;
#pragma unroll
            for (int di = 0; di < 3; di++) {
                const int ht = hh + 1 - di;
                float m = (ht >= 0 && ht < H) ? 1.f : 0.f;
                if (hh == 1     && ht == 0    ) m += 1.f;
                if (hh == H - 2 && ht == H - 1) m += 1.f;
                float cy  = fminf(fmaxf((float)ht - sy, 0.f), (float)(H - 1));
                float iy  = cy * ((float)(H - 1) / (float)H);
                float y0f = floorf(iy);
                y0a[di] = (int)y0f; fya[di] = iy - y0f; mya[di] = m;
                if (m != 0.f) qmin = min(qmin, y0a[di]);
            }
            const int py = min(qmin, H - 4);
#pragma unroll
            for (int di = 0; di < 3; di++) {
                const int l = min(max(y0a[di] - py, 0), 2);
                float g[4];
#pragma unroll
                for (int r = 0; r < 4; r++)
                    g[r] = mya[di] * ((r == l) ? (1.f - fya[di])
                                    : ((r == l + 1) ? fya[di] : 0.f));
                ub[6 + di] = h2pack(g[0], g[1]);
                ub[9 + di] = h2pack(g[2], g[3]);
            }
            ub[12] = (unsigned)((py * WP + (px >> 1)) * 4) | (parity << 31);
        }
        uint4* dst = (uint4*)(upw + u * UPW);
        dst[0] = make_uint4(ub[0], ub[1], ub[2],  ub[3]);
        dst[1] = make_uint4(ub[4], ub[5], ub[6],  ub[7]);
        dst[2] = make_uint4(ub[8], ub[9], ub[10], ub[11]);
        dst[3] = make_uint4(ub[12], 0u, 0u, 0u);
    }
    __syncthreads();

    // ---------- phase B ----------
    const int cg = tid & 3;
    const int k  = (tid & 31) >> 2;   // unit index within warp (0..7)

    for (int wave = 0; wave < NWAVE; wave++) {
        const int u = wave * 64 + (tid >> 2);

        const uint4* src = (const uint4*)(upw + u * UPW);
        const uint4 q0 = src[0];
        const uint4 q1 = src[1];
        const uint4 q2 = src[2];
        const uint4 q3 = src[3];

        const unsigned wxlo[3] = {q0.x, q0.z, q1.x};   // dj: (w0,w1)
        const unsigned wxhi[3] = {q0.y, q0.w, q1.y};   // dj: (w2,w3)
        const unsigned wy01v[3] = {q1.z, q1.w, q2.x};
        const unsigned wy23v[3] = {q2.y, q2.z, q2.w};
        const int  base   = (int)(q3.x & 0x7fffffffu) + cg;
        const bool parity = (q3.x >> 31) != 0u;
        const int ur = u / HALO, uc = u % HALO;

        const __half2 hz = __float2half2_rn(0.f);
        __half2 o01[9], o23[9];
#pragma unroll
        for (int p = 0; p < 9; p++) { o01[p] = hz; o23[p] = hz; }

#pragma unroll
        for (int r = 0; r < 4; r++) {
            const int qb = base + r * (WP * 4);
            const uint4 P0 = __ldg(g_h4 + qb);
            const uint4 P1 = __ldg(g_h4 + qb + 4);
            const uint4 P2 = parity ? __ldg(g_h4 + qb + 8)
                                    : make_uint4(0u, 0u, 0u, 0u);

            // columns (parity select, uniform per thread)
            // even: C = [P0.even, P0.odd, P1.even, P1.odd]
            // odd : C = [P0.odd,  P1.even, P1.odd, P2.even]
            const __half2 C01_0 = u2h(parity ? P0.z : P0.x);
            const __half2 C01_1 = u2h(parity ? P1.x : P0.z);
            const __half2 C01_2 = u2h(parity ? P1.z : P1.x);
            const __half2 C01_3 = u2h(parity ? P2.x : P1.z);
            const __half2 C23_0 = u2h(parity ? P0.w : P0.y);
            const __half2 C23_1 = u2h(parity ? P1.y : P0.w);
            const __half2 C23_2 = u2h(parity ? P1.w : P1.y);
            const __half2 C23_3 = u2h(parity ? P2.y : P1.w);

#pragma unroll
            for (int dj = 0; dj < 3; dj++) {
                const __half2 w0 = __low2half2 (u2h(wxlo[dj]));
                const __half2 w1 = __high2half2(u2h(wxlo[dj]));
                const __half2 w2 = __low2half2 (u2h(wxhi[dj]));
                const __half2 w3 = __high2half2(u2h(wxhi[dj]));

                __half2 t01 = __hmul2(C01_0, w0);
                __half2 t23 = __hmul2(C23_0, w0);
                t01 = __hfma2(C01_1, w1, t01);
                t23 = __hfma2(C23_1, w1, t23);
                t01 = __hfma2(C01_2, w2, t01);
                t23 = __hfma2(C23_2, w2, t23);
                t01 = __hfma2(C01_3, w3, t01);
                t23 = __hfma2(C23_3, w3, t23);
#pragma unroll
                for (int di = 0; di < 3; di++) {
                    const unsigned wsel = (r < 2) ? wy01v[di] : wy23v[di];
                    const __half2 g = ((r & 1) == 0) ? __low2half2(u2h(wsel))
                                                     : __high2half2(u2h(wsel));
                    o01[di*3+dj] = __hfma2(t01, g, o01[di*3+dj]);
                    o23[di*3+dj] = __hfma2(t23, g, o23[di*3+dj]);
                }
            }
        }

        // ---- scatter: 3 comb phases + 1 merged leftover phase ----
#pragma unroll
        for (int di = 0; di < 3; di++) {
            const int row = ur - di;
            const unsigned a1 = __shfl_down_sync(0xffffffffu, h2u(o01[di*3+1]), 4);
            const unsigned b1 = __shfl_down_sync(0xffffffffu, h2u(o23[di*3+1]), 4);
            const unsigned a2 = __shfl_down_sync(0xffffffffu, h2u(o01[di*3+2]), 8);
            const unsigned b2 = __shfl_down_sync(0xffffffffu, h2u(o23[di*3+2]), 8);
            __half2 c01 = o01[di*3+0];
            __half2 c23 = o23[di*3+0];
            if (k <= 6) { c01 = __hadd2(c01, u2h(a1)); c23 = __hadd2(c23, u2h(b1)); }
            if (k <= 5) { c01 = __hadd2(c01, u2h(a2)); c23 = __hadd2(c23, u2h(b2)); }
            if ((unsigned)row < (unsigned)TILE && (unsigned)uc < (unsigned)TILE) {
                const int idx = row * TILE + uc;
                const float2 lo = __half22float2(c01);
                const float2 hi = __half22float2(c23);
                float4 v = acc[cg][idx];
                v.x += lo.x; v.y += lo.y; v.z += hi.x; v.w += hi.y;
                acc[cg][idx] = v;
            }
            __syncthreads();
        }

        // merged leftover phase (k==0 lanes; cells race-free across warps/di)
#pragma unroll
        for (int di = 0; di < 3; di++) {
            const int row = ur - di;
            const unsigned la = __shfl_down_sync(0xffffffffu, h2u(o01[di*3+2]), 4);
            const unsigned lb = __shfl_down_sync(0xffffffffu, h2u(o23[di*3+2]), 4);
            if (k == 0) {
                if ((unsigned)row < (unsigned)TILE &&
                    (unsigned)(uc - 1) < (unsigned)TILE) {
                    __half2 A01h = __hadd2(o01[di*3+1], u2h(la));
                    __half2 A23h = __hadd2(o23[di*3+1], u2h(lb));
                    const int idx = row * TILE + (uc - 1);
                    const float2 lo = __half22float2(A01h);
                    const float2 hi = __half22float2(A23h);
                    float4 v = acc[cg][idx];
                    v.x += lo.x; v.y += lo.y; v.z += hi.x; v.w += hi.y;
                    acc[cg][idx] = v;
                }
                if ((unsigned)row < (unsigned)TILE &&
                    (unsigned)(uc - 2) < (unsigned)TILE) {
                    const int idx = row * TILE + (uc - 2);
                    const float2 lo = __half22float2(o01[di*3+2]);
                    const float2 hi = __half22float2(o23[di*3+2]);
                    float4 v = acc[cg][idx];
                    v.x += lo.x; v.y += lo.y; v.z += hi.x; v.w += hi.y;
                    acc[cg][idx] = v;
                }
            }
        }
        __syncthreads();
    }

    // ---------- writeback ----------
    const int ph = tid >> 4, pw = tid & 15;
    const int gidx = (h0 + ph) * W + (w0 + pw);
    const float inv9 = 1.0f / 9.0f;
#pragma unroll
    for (int kk = 0; kk < 4; kk++) {
        const float4 a = acc[kk][tid];
        out[(4*kk + 0) * HW + gidx] = a.x * inv9;
        out[(4*kk + 1) * HW + gidx] = a.y * inv9;
        out[(4*kk + 2) * HW + gidx] = a.z * inv9;
        out[(4*kk + 3) * HW + gidx] = a.w * inv9;
    }
}

extern "C" void kernel_launch(void* const* d_in, const int* in_sizes, int n_in,
                              void* d_out, int out_size)
{
    const float* img  = (const float*)d_in[0];
    const float* offx = (const float*)d_in[1];
    const float* offy = (const float*)d_in[2];
    float* out = (float*)d_out;

    transpose_kernel<<<HW / TP_PIX, 256>>>(img);

    dim3 grid(W / TILE, H / TILE);
    recon_scatter<<<grid, 256>>>(offx, offy, out);
}

// round 12
// speedup vs baseline: 1.4513x; 1.0349x over previous
#include <cuda_runtime.h>
#include <cuda_fp16.h>

#define W 960
#define H 512
#define C 16
#define HW (H * W)
#define WP (W / 2)

// pair-packed fp16 image: uint4 index = pairIdx*4 + cg,
// payload = 8 halves: [pixEven ch0..1, pixEven ch2..3, pixOdd ch0..1, pixOdd ch2..3]
__device__ uint4 g_h4[HW * 2];

__device__ __forceinline__ unsigned h2pack(float a, float b) {
    __half2 h = __floats2half2_rn(a, b);
    return *reinterpret_cast<unsigned*>(&h);
}
__device__ __forceinline__ __half2 u2h(unsigned v) {
    return *reinterpret_cast<__half2*>(&v);
}
__device__ __forceinline__ unsigned h2u(__half2 h) {
    return *reinterpret_cast<unsigned*>(&h);
}

// ---------------- transpose+pack CHW fp32 -> pair-packed fp16 ----------------
// smem layout tile[k][v][c]: pixel = pix0 + v*4 + k, channel c.
// store: lanes vary v, stride 17 words -> 17v mod 32 all distinct (conflict-free)
#define TP_PIX 128
__global__ __launch_bounds__(256) void transpose_kernel(const float* __restrict__ img)
{
    __shared__ float tile[4][32][C + 1];
    const int pix0 = blockIdx.x * TP_PIX;

#pragma unroll
    for (int i = 0; i < 2; i++) {
        const int idx = threadIdx.x + i * 256;
        const int c = idx >> 5;          // 0..15 (same for whole warp)
        const int v = idx & 31;          // lane
        const float4 d = *(const float4*)(img + c * HW + pix0 + v * 4);
        tile[0][v][c] = d.x;
        tile[1][v][c] = d.y;
        tile[2][v][c] = d.z;
        tile[3][v][c] = d.w;
    }
    __syncthreads();

    {
        const int p2l = threadIdx.x >> 2;    // 0..63 local pair
        const int cg  = threadIdx.x & 3;
        const int pe  = 2 * p2l;             // even pixel
        const int po  = 2 * p2l + 1;         // odd pixel
        const float* re0 = tile[pe & 3][pe >> 2];
        const float* ro0 = tile[po & 3][po >> 2];
        uint4 v;
        v.x = h2pack(re0[cg*4+0], re0[cg*4+1]);
        v.y = h2pack(re0[cg*4+2], re0[cg*4+3]);
        v.z = h2pack(ro0[cg*4+0], ro0[cg*4+1]);
        v.w = h2pack(ro0[cg*4+2], ro0[cg*4+3]);
        g_h4[((pix0 >> 1) + p2l) * 4 + cg] = v;
    }
}

// ---------------- scatter-patch reconstruct ----------------
#define TILE 16
#define HALO 18
#define NUNIT (HALO * HALO)   /* 324 */
#define NUPAD 328             /* max u touched by an active warp = 327 */
#define NWAVE 6
#define ACC_PITCH 257
#define UPW 20                /* 80B stride: 16B-aligned, conflict-free */

__global__ __launch_bounds__(256, 4) void recon_scatter(
    const float* __restrict__ offx,
    const float* __restrict__ offy,
    float* __restrict__ out)
{
    __shared__ float4 acc[4][ACC_PITCH];
    __shared__ unsigned upw[NUPAD * UPW];

    const int tid = threadIdx.x;
    const int h0 = blockIdx.y * TILE;
    const int w0 = blockIdx.x * TILE;

    for (int i = tid; i < 4 * ACC_PITCH; i += 256)
        ((float4*)acc)[i] = make_float4(0.f, 0.f, 0.f, 0.f);

    // ---------- phase A: per-unit params ----------
    for (int u = tid; u < NUPAD; u += 256) {
        const int ur = u / HALO, uc = u % HALO;
        const int hh = h0 - 1 + ur, ww = w0 - 1 + uc;
        unsigned ub[13];
#pragma unroll
        for (int k = 0; k < 13; k++) ub[k] = 0u;

        if (u < NUNIT && hh >= 0 && hh < H && ww >= 0 && ww < W) {
            const float sx = __ldg(offx + hh * W + ww);
            const float sy = __ldg(offy + hh * W + ww);

            // ---- x: 4-wide unaligned window ----
            int x0a[3]; float fxa[3], ma[3]; int pmin = W;
#pragma unroll
            for (int dj = 0; dj < 3; dj++) {
                const int wt = ww + 1 - dj;
                float m = (wt >= 0 && wt < W) ? 1.f : 0.f;
                if (ww == 1     && wt == 0    ) m += 1.f;
                if (ww == W - 2 && wt == W - 1) m += 1.f;
                float cx  = fminf(fmaxf((float)wt - sx, 0.f), (float)(W - 1));
                float ix  = cx * ((float)(W - 1) / (float)W);
                float x0f = floorf(ix);
                x0a[dj] = (int)x0f; fxa[dj] = ix - x0f; ma[dj] = m;
                if (m != 0.f) pmin = min(pmin, x0a[dj]);
            }
            const int px = min(max(pmin, 0), W - 4);
            const unsigned parity = (unsigned)(px & 1);
#pragma unroll
            for (int dj = 0; dj < 3; dj++) {
                const int l = min(max(x0a[dj] - px, 0), 2);
                float v[4];
#pragma unroll
                for (int c = 0; c < 4; c++)
                    v[c] = ma[dj] * ((c == l) ? (1.f - fxa[dj])
                                   : ((c == l + 1) ? fxa[dj] : 0.f));
                ub[dj * 2 + 0] = h2pack(v[0], v[1]);
                ub[dj * 2 + 1] = h2pack(v[2], v[3]);
            }

            // ---- y ----
            int y0a[3]; float fya[3], mya[3]; int qmin = H;
#pragma unroll
            for (int di = 0; di < 3; di++) {
                const int ht = hh + 1 - di;
                float m = (ht >= 0 && ht < H) ? 1.f : 0.f;
                if (hh == 1     && ht == 0    ) m += 1.f;
                if (hh == H - 2 && ht == H - 1) m += 1.f;
                float cy  = fminf(fmaxf((float)ht - sy, 0.f), (float)(H - 1));
                float iy  = cy * ((float)(H - 1) / (float)H);
                float y0f = floorf(iy);
                y0a[di] = (int)y0f; fya[di] = iy - y0f; mya[di] = m;
                if (m != 0.f) qmin = min(qmin, y0a[di]);
            }
            const int py = min(qmin, H - 4);
#pragma unroll
            for (int di = 0; di < 3; di++) {
                const int l = min(max(y0a[di] - py, 0), 2);
                float g[4];
#pragma unroll
                for (int r = 0; r < 4; r++)
                    g[r] = mya[di] * ((r == l) ? (1.f - fya[di])
                                    : ((r == l + 1) ? fya[di] : 0.f));
                ub[6 + di] = h2pack(g[0], g[1]);
                ub[9 + di] = h2pack(g[2], g[3]);
            }
            ub[12] = (unsigned)((py * WP + (px >> 1)) * 4) | (parity << 31);
        }
        uint4* dst = (uint4*)(upw + u * UPW);
        dst[0] = make_uint4(ub[0], ub[1], ub[2],  ub[3]);
        dst[1] = make_uint4(ub[4], ub[5], ub[6],  ub[7]);
        dst[2] = make_uint4(ub[8], ub[9], ub[10], ub[11]);
        dst[3] = make_uint4(ub[12], 0u, 0u, 0u);
    }
    __syncthreads();

    // ---------- phase B ----------
    const int cg = tid & 3;
    const int k  = (tid & 31) >> 2;   // unit index within warp (0..7)

    for (int wave = 0; wave < NWAVE; wave++) {
        // warp-uniform: does this warp own any real unit this wave?
        const bool wactive = (wave * 64 + ((tid >> 5) << 3)) < NUNIT;
        const int u = wave * 64 + (tid >> 2);   // <= 383; reads guarded by wactive (u<=327)

        int ur = 0, uc = 0;
        const __half2 hz = __float2half2_rn(0.f);
        __half2 o01[9], o23[9];
#pragma unroll
        for (int p = 0; p < 9; p++) { o01[p] = hz; o23[p] = hz; }

        if (wactive) {
            const uint4* src = (const uint4*)(upw + u * UPW);
            const uint4 q0 = src[0];
            const uint4 q1 = src[1];
            const uint4 q2 = src[2];
            const uint4 q3 = src[3];

            const unsigned wxlo[3] = {q0.x, q0.z, q1.x};
            const unsigned wxhi[3] = {q0.y, q0.w, q1.y};
            const unsigned wy01v[3] = {q1.z, q1.w, q2.x};
            const unsigned wy23v[3] = {q2.y, q2.z, q2.w};
            const int  base   = (int)(q3.x & 0x7fffffffu) + cg;
            const bool parity = (q3.x >> 31) != 0u;
            ur = u / HALO; uc = u % HALO;

#pragma unroll
            for (int r = 0; r < 4; r++) {
                const int qb = base + r * (WP * 4);
                const uint4 P0 = __ldg(g_h4 + qb);
                const uint4 P1 = __ldg(g_h4 + qb + 4);
                const uint4 P2 = parity ? __ldg(g_h4 + qb + 8)
                                        : make_uint4(0u, 0u, 0u, 0u);

                const __half2 C01_0 = u2h(parity ? P0.z : P0.x);
                const __half2 C01_1 = u2h(parity ? P1.x : P0.z);
                const __half2 C01_2 = u2h(parity ? P1.z : P1.x);
                const __half2 C01_3 = u2h(parity ? P2.x : P1.z);
                const __half2 C23_0 = u2h(parity ? P0.w : P0.y);
                const __half2 C23_1 = u2h(parity ? P1.y : P0.w);
                const __half2 C23_2 = u2h(parity ? P1.w : P1.y);
                const __half2 C23_3 = u2h(parity ? P2.y : P1.w);

#pragma unroll
                for (int dj = 0; dj < 3; dj++) {
                    const __half2 w0 = __low2half2 (u2h(wxlo[dj]));
                    const __half2 w1 = __high2half2(u2h(wxlo[dj]));
                    const __half2 w2 = __low2half2 (u2h(wxhi[dj]));
                    const __half2 w3 = __high2half2(u2h(wxhi[dj]));

                    __half2 t01 = __hmul2(C01_0, w0);
                    __half2 t23 = __hmul2(C23_0, w0);
                    t01 = __hfma2(C01_1, w1, t01);
                    t23 = __hfma2(C23_1, w1, t23);
                    t01 = __hfma2(C01_2, w2, t01);
                    t23 = __hfma2(C23_2, w2, t23);
                    t01 = __hfma2(C01_3, w3, t01);
                    t23 = __hfma2(C23_3, w3, t23);
#pragma unroll
                    for (int di = 0; di < 3; di++) {
                        const unsigned wsel = (r < 2) ? wy01v[di] : wy23v[di];
                        const __half2 g = ((r & 1) == 0) ? __low2half2(u2h(wsel))
                                                         : __high2half2(u2h(wsel));
                        o01[di*3+dj] = __hfma2(t01, g, o01[di*3+dj]);
                        o23[di*3+dj] = __hfma2(t23, g, o23[di*3+dj]);
                    }
                }
            }
        }

        // ---- scatter: 3 comb phases + 1 merged leftover phase ----
#pragma unroll
        for (int di = 0; di < 3; di++) {
            if (wactive) {
                const int row = ur - di;
                const unsigned a1 = __shfl_down_sync(0xffffffffu, h2u(o01[di*3+1]), 4);
                const unsigned b1 = __shfl_down_sync(0xffffffffu, h2u(o23[di*3+1]), 4);
                const unsigned a2 = __shfl_down_sync(0xffffffffu, h2u(o01[di*3+2]), 8);
                const unsigned b2 = __shfl_down_sync(0xffffffffu, h2u(o23[di*3+2]), 8);
                __half2 c01 = o01[di*3+0];
                __half2 c23 = o23[di*3+0];
                if (k <= 6) { c01 = __hadd2(c01, u2h(a1)); c23 = __hadd2(c23, u2h(b1)); }
                if (k <= 5) { c01 = __hadd2(c01, u2h(a2)); c23 = __hadd2(c23, u2h(b2)); }
                if ((unsigned)row < (unsigned)TILE && (unsigned)uc < (unsigned)TILE) {
                    const int idx = row * TILE + uc;
                    const float2 lo = __half22float2(c01);
                    const float2 hi = __half22float2(c23);
                    float4 v = acc[cg][idx];
                    v.x += lo.x; v.y += lo.y; v.z += hi.x; v.w += hi.y;
                    acc[cg][idx] = v;
                }
            }
            __syncthreads();
        }

        if (wactive) {
#pragma unroll
            for (int di = 0; di < 3; di++) {
                const int row = ur - di;
                const unsigned la = __shfl_down_sync(0xffffffffu, h2u(o01[di*3+2]), 4);
                const unsigned lb = __shfl_down_sync(0xffffffffu, h2u(o23[di*3+2]), 4);
                if (k == 0) {
                    if ((unsigned)row < (unsigned)TILE &&
                        (unsigned)(uc - 1) < (unsigned)TILE) {
                        __half2 A01h = __hadd2(o01[di*3+1], u2h(la));
                        __half2 A23h = __hadd2(o23[di*3+1], u2h(lb));
                        const int idx = row * TILE + (uc - 1);
                        const float2 lo = __half22float2(A01h);
                        const float2 hi = __half22float2(A23h);
                        float4 v = acc[cg][idx];
                        v.x += lo.x; v.y += lo.y; v.z += hi.x; v.w += hi.y;
                        acc[cg][idx] = v;
                    }
                    if ((unsigned)row < (unsigned)TILE &&
                        (unsigned)(uc - 2) < (unsigned)TILE) {
                        const int idx = row * TILE + (uc - 2);
                        const float2 lo = __half22float2(o01[di*3+2]);
                        const float2 hi = __half22float2(o23[di*3+2]);
                        float4 v = acc[cg][idx];
                        v.x += lo.x; v.y += lo.y; v.z += hi.x; v.w += hi.y;
                        acc[cg][idx] = v;
                    }
                }
            }
        }
        __syncthreads();
    }

    // ---------- writeback ----------
    const int ph = tid >> 4, pw = tid & 15;
    const int gidx = (h0 + ph) * W + (w0 + pw);
    const float inv9 = 1.0f / 9.0f;
#pragma unroll
    for (int kk = 0; kk < 4; kk++) {
        const float4 a = acc[kk][tid];
        out[(4*kk + 0) * HW + gidx] = a.x * inv9;
        out[(4*kk + 1) * HW + gidx] = a.y * inv9;
        out[(4*kk + 2) * HW + gidx] = a.z * inv9;
        out[(4*kk + 3) * HW + gidx] = a.w * inv9;
    }
}

extern "C" void kernel_launch(void* const* d_in, const int* in_sizes, int n_in,
                              void* d_out, int out_size)
{
    const float* img  = (const float*)d_in[0];
    const float* offx = (const float*)d_in[1];
    const float* offy = (const float*)d_in[2];
    float* out = (float*)d_out;

    transpose_kernel<<<HW / TP_PIX, 256>>>(img);

    dim3 grid(W / TILE, H / TILE);
    recon_scatter<<<grid, 256>>>(offx, offy, out);
}

// round 13
// speedup vs baseline: 1.6646x; 1.1470x over previous
#include <cuda_runtime.h>
#include <cuda_fp16.h>

#define W 960
#define H 512
#define C 16
#define HW (H * W)
#define WP (W / 2)

// pair-packed fp16 image: uint4 index = pairIdx*4 + cg,
// payload = 8 halves: [pixEven ch0..1, pixEven ch2..3, pixOdd ch0..1, pixOdd ch2..3]
__device__ uint4 g_h4[HW * 2];

__device__ __forceinline__ unsigned h2pack(float a, float b) {
    __half2 h = __floats2half2_rn(a, b);
    return *reinterpret_cast<unsigned*>(&h);
}
__device__ __forceinline__ __half2 u2h(unsigned v) {
    return *reinterpret_cast<__half2*>(&v);
}
__device__ __forceinline__ unsigned h2u(__half2 h) {
    return *reinterpret_cast<unsigned*>(&h);
}

// ---------------- transpose+pack CHW fp32 -> pair-packed fp16 ----------------
#define TP_PIX 128
__global__ __launch_bounds__(256) void transpose_kernel(const float* __restrict__ img)
{
    __shared__ float tile[4][32][C + 1];
    const int pix0 = blockIdx.x * TP_PIX;

#pragma unroll
    for (int i = 0; i < 2; i++) {
        const int idx = threadIdx.x + i * 256;
        const int c = idx >> 5;
        const int v = idx & 31;
        const float4 d = *(const float4*)(img + c * HW + pix0 + v * 4);
        tile[0][v][c] = d.x;
        tile[1][v][c] = d.y;
        tile[2][v][c] = d.z;
        tile[3][v][c] = d.w;
    }
    __syncthreads();

    {
        const int p2l = threadIdx.x >> 2;
        const int cg  = threadIdx.x & 3;
        const int pe  = 2 * p2l;
        const int po  = 2 * p2l + 1;
        const float* re0 = tile[pe & 3][pe >> 2];
        const float* ro0 = tile[po & 3][po >> 2];
        uint4 v;
        v.x = h2pack(re0[cg*4+0], re0[cg*4+1]);
        v.y = h2pack(re0[cg*4+2], re0[cg*4+3]);
        v.z = h2pack(ro0[cg*4+0], ro0[cg*4+1]);
        v.w = h2pack(ro0[cg*4+2], ro0[cg*4+3]);
        g_h4[((pix0 >> 1) + p2l) * 4 + cg] = v;
    }
}

// ---------------- scatter-patch reconstruct (barrier-free stores) ----------------
#define TILE 16
#define NCELL (TILE * TILE)
#define HALO 18
#define NUNIT (HALO * HALO)   /* 324 */
#define NUPAD 328
#define NWAVE 3               /* 512 threads: 128 units per wave */
#define THREADS 512
#define UPW 20                /* 80B stride: 16B-aligned, conflict-free */

__global__ __launch_bounds__(THREADS, 2) void recon_scatter(
    const float* __restrict__ offx,
    const float* __restrict__ offy,
    float* __restrict__ out)
{
    __shared__ unsigned upw[NUPAD * UPW];          // 26.2 KB
    __shared__ unsigned comb01[3][NCELL * 4];      // [di][cell*4+cg] ch0,1
    __shared__ unsigned comb23[3][NCELL * 4];      // [di][cell*4+cg] ch2,3
    __shared__ unsigned left01[NCELL * 4];         // leftover (store-once, proven)
    __shared__ unsigned left23[NCELL * 4];

    const int tid = threadIdx.x;
    const int h0 = blockIdx.y * TILE;
    const int w0 = blockIdx.x * TILE;

    // zero-init leftover planes only (comb cells are all written exactly once)
    for (int i = tid; i < NCELL * 4; i += THREADS) { left01[i] = 0u; left23[i] = 0u; }

    // ---------- phase A: per-unit params (single pass, 512 >= 328) ----------
    if (tid < NUPAD) {
        const int u = tid;
        const int ur = u / HALO, uc = u % HALO;
        const int hh = h0 - 1 + ur, ww = w0 - 1 + uc;
        unsigned ub[13];
#pragma unroll
        for (int k = 0; k < 13; k++) ub[k] = 0u;

        if (u < NUNIT && hh >= 0 && hh < H && ww >= 0 && ww < W) {
            const float sx = __ldg(offx + hh * W + ww);
            const float sy = __ldg(offy + hh * W + ww);

            // ---- x: 4-wide unaligned window ----
            int x0a[3]; float fxa[3], ma[3]; int pmin = W;
#pragma unroll
            for (int dj = 0; dj < 3; dj++) {
                const int wt = ww + 1 - dj;
                float m = (wt >= 0 && wt < W) ? 1.f : 0.f;
                if (ww == 1     && wt == 0    ) m += 1.f;
                if (ww == W - 2 && wt == W - 1) m += 1.f;
                float cx  = fminf(fmaxf((float)wt - sx, 0.f), (float)(W - 1));
                float ix  = cx * ((float)(W - 1) / (float)W);
                float x0f = floorf(ix);
                x0a[dj] = (int)x0f; fxa[dj] = ix - x0f; ma[dj] = m;
                if (m != 0.f) pmin = min(pmin, x0a[dj]);
            }
            const int px = min(max(pmin, 0), W - 4);
            const unsigned parity = (unsigned)(px & 1);
#pragma unroll
            for (int dj = 0; dj < 3; dj++) {
                const int l = min(max(x0a[dj] - px, 0), 2);
                float v[4];
#pragma unroll
                for (int c = 0; c < 4; c++)
                    v[c] = ma[dj] * ((c == l) ? (1.f - fxa[dj])
                                   : ((c == l + 1) ? fxa[dj] : 0.f));
                ub[dj * 2 + 0] = h2pack(v[0], v[1]);
                ub[dj * 2 + 1] = h2pack(v[2], v[3]);
            }

            // ---- y ----
            int y0a[3]; float fya[3], mya[3]; int qmin = H;
#pragma unroll
            for (int di = 0; di < 3; di++) {
                const int ht = hh + 1 - di;
                float m = (ht >= 0 && ht < H) ? 1.f : 0.f;
                if (hh == 1     && ht == 0    ) m += 1.f;
                if (hh == H - 2 && ht == H - 1) m += 1.f;
                float cy  = fminf(fmaxf((float)ht - sy, 0.f), (float)(H - 1));
                float iy  = cy * ((float)(H - 1) / (float)H);
                float y0f = floorf(iy);
                y0a[di] = (int)y0f; fya[di] = iy - y0f; mya[di] = m;
                if (m != 0.f) qmin = min(qmin, y0a[di]);
            }
            const int py = min(qmin, H - 4);
#pragma unroll
            for (int di = 0; di < 3; di++) {
                const int l = min(max(y0a[di] - py, 0), 2);
                float g[4];
#pragma unroll
                for (int r = 0; r < 4; r++)
                    g[r] = mya[di] * ((r == l) ? (1.f - fya[di])
                                    : ((r == l + 1) ? fya[di] : 0.f));
                ub[6 + di] = h2pack(g[0], g[1]);
                ub[9 + di] = h2pack(g[2], g[3]);
            }
            ub[12] = (unsigned)((py * WP + (px >> 1)) * 4) | (parity << 31);
        }
        uint4* dst = (uint4*)(upw + u * UPW);
        dst[0] = make_uint4(ub[0], ub[1], ub[2],  ub[3]);
        dst[1] = make_uint4(ub[4], ub[5], ub[6],  ub[7]);
        dst[2] = make_uint4(ub[8], ub[9], ub[10], ub[11]);
        dst[3] = make_uint4(ub[12], 0u, 0u, 0u);
    }
    __syncthreads();

    // ---------- phase B: 3 waves, NO barriers (all writes store-once) ----------
    const int cg = tid & 3;
    const int k  = (tid & 31) >> 2;

    for (int wave = 0; wave < NWAVE; wave++) {
        const bool wactive = (wave * 128 + ((tid >> 5) << 3)) < NUNIT;
        if (!wactive) continue;          // warp-uniform; no barriers below

        const int u = wave * 128 + (tid >> 2);   // <= 327 for active warps

        const uint4* src = (const uint4*)(upw + u * UPW);
        const uint4 q0 = src[0];
        const uint4 q1 = src[1];
        const uint4 q2 = src[2];
        const uint4 q3 = src[3];

        const unsigned wxlo[3] = {q0.x, q0.z, q1.x};
        const unsigned wxhi[3] = {q0.y, q0.w, q1.y};
        const unsigned wy01v[3] = {q1.z, q1.w, q2.x};
        const unsigned wy23v[3] = {q2.y, q2.z, q2.w};
        const int  base   = (int)(q3.x & 0x7fffffffu) + cg;
        const bool parity = (q3.x >> 31) != 0u;
        const int ur = u / HALO, uc = u % HALO;

        const __half2 hz = __float2half2_rn(0.f);
        __half2 o01[9], o23[9];
#pragma unroll
        for (int p = 0; p < 9; p++) { o01[p] = hz; o23[p] = hz; }

#pragma unroll
        for (int r = 0; r < 4; r++) {
            const int qb = base + r * (WP * 4);
            const uint4 P0 = __ldg(g_h4 + qb);
            const uint4 P1 = __ldg(g_h4 + qb + 4);
            const uint4 P2 = parity ? __ldg(g_h4 + qb + 8)
                                    : make_uint4(0u, 0u, 0u, 0u);

            const __half2 C01_0 = u2h(parity ? P0.z : P0.x);
            const __half2 C01_1 = u2h(parity ? P1.x : P0.z);
            const __half2 C01_2 = u2h(parity ? P1.z : P1.x);
            const __half2 C01_3 = u2h(parity ? P2.x : P1.z);
            const __half2 C23_0 = u2h(parity ? P0.w : P0.y);
            const __half2 C23_1 = u2h(parity ? P1.y : P0.w);
            const __half2 C23_2 = u2h(parity ? P1.w : P1.y);
            const __half2 C23_3 = u2h(parity ? P2.y : P1.w);

#pragma unroll
            for (int dj = 0; dj < 3; dj++) {
                const __half2 w0 = __low2half2 (u2h(wxlo[dj]));
                const __half2 w1 = __high2half2(u2h(wxlo[dj]));
                const __half2 w2 = __low2half2 (u2h(wxhi[dj]));
                const __half2 w3 = __high2half2(u2h(wxhi[dj]));

                __half2 t01 = __hmul2(C01_0, w0);
                __half2 t23 = __hmul2(C23_0, w0);
                t01 = __hfma2(C01_1, w1, t01);
                t23 = __hfma2(C23_1, w1, t23);
                t01 = __hfma2(C01_2, w2, t01);
                t23 = __hfma2(C23_2, w2, t23);
                t01 = __hfma2(C01_3, w3, t01);
                t23 = __hfma2(C23_3, w3, t23);
#pragma unroll
                for (int di = 0; di < 3; di++) {
                    const unsigned wsel = (r < 2) ? wy01v[di] : wy23v[di];
                    const __half2 g = ((r & 1) == 0) ? __low2half2(u2h(wsel))
                                                     : __high2half2(u2h(wsel));
                    o01[di*3+dj] = __hfma2(t01, g, o01[di*3+dj]);
                    o23[di*3+dj] = __hfma2(t23, g, o23[di*3+dj]);
                }
            }
        }

        // ---- comb stores (store-once per [di] array; conflict-free STS.32) ----
#pragma unroll
        for (int di = 0; di < 3; di++) {
            const int row = ur - di;
            const unsigned a1 = __shfl_down_sync(0xffffffffu, h2u(o01[di*3+1]), 4);
            const unsigned b1 = __shfl_down_sync(0xffffffffu, h2u(o23[di*3+1]), 4);
            const unsigned a2 = __shfl_down_sync(0xffffffffu, h2u(o01[di*3+2]), 8);
            const unsigned b2 = __shfl_down_sync(0xffffffffu, h2u(o23[di*3+2]), 8);
            __half2 c01 = o01[di*3+0];
            __half2 c23 = o23[di*3+0];
            if (k <= 6) { c01 = __hadd2(c01, u2h(a1)); c23 = __hadd2(c23, u2h(b1)); }
            if (k <= 5) { c01 = __hadd2(c01, u2h(a2)); c23 = __hadd2(c23, u2h(b2)); }
            if ((unsigned)row < (unsigned)TILE && (unsigned)uc < (unsigned)TILE) {
                const int a = (row * TILE + uc) * 4 + cg;
                comb01[di][a] = h2u(c01);
                comb23[di][a] = h2u(c23);
            }
        }

        // ---- leftovers (k==0 lanes; all cells distinct across block — store) ----
#pragma unroll
        for (int di = 0; di < 3; di++) {
            const int row = ur - di;
            const unsigned la = __shfl_down_sync(0xffffffffu, h2u(o01[di*3+2]), 4);
            const unsigned lb = __shfl_down_sync(0xffffffffu, h2u(o23[di*3+2]), 4);
            if (k == 0) {
                if ((unsigned)row < (unsigned)TILE &&
                    (unsigned)(uc - 1) < (unsigned)TILE) {
                    const int a = (row * TILE + (uc - 1)) * 4 + cg;
                    left01[a] = h2u(__hadd2(o01[di*3+1], u2h(la)));
                    left23[a] = h2u(__hadd2(o23[di*3+1], u2h(lb)));
                }
                if ((unsigned)row < (unsigned)TILE &&
                    (unsigned)(uc - 2) < (unsigned)TILE) {
                    const int a = (row * TILE + (uc - 2)) * 4 + cg;
                    left01[a] = h2u(o01[di*3+2]);
                    left23[a] = h2u(o23[di*3+2]);
                }
            }
        }
    }
    __syncthreads();

    // ---------- writeback: sum 3 comb arrays + leftover in fp32 ----------
    const float inv9 = 1.0f / 9.0f;
#pragma unroll
    for (int pass = 0; pass < 2; pass++) {
        const int a = pass * THREADS + tid;       // = cell*4 + cg, conflict-free
        const int cell = a >> 2;
        const int acg  = a & 3;
        const int gidx = (h0 + (cell >> 4)) * W + (w0 + (cell & 15));

        float2 s01 = __half22float2(u2h(left01[a]));
        float2 s23 = __half22float2(u2h(left23[a]));
#pragma unroll
        for (int di = 0; di < 3; di++) {
            const float2 c0 = __half22float2(u2h(comb01[di][a]));
            const float2 c2 = __half22float2(u2h(comb23[di][a]));
            s01.x += c0.x; s01.y += c0.y;
            s23.x += c2.x; s23.y += c2.y;
        }
        out[(4*acg + 0) * HW + gidx] = s01.x * inv9;
        out[(4*acg + 1) * HW + gidx] = s01.y * inv9;
        out[(4*acg + 2) * HW + gidx] = s23.x * inv9;
        out[(4*acg + 3) * HW + gidx] = s23.y * inv9;
    }
}

extern "C" void kernel_launch(void* const* d_in, const int* in_sizes, int n_in,
                              void* d_out, int out_size)
{
    const float* img  = (const float*)d_in[0];
    const float* offx = (const float*)d_in[1];
    const float* offy = (const float*)d_in[2];
    float* out = (float*)d_out;

    transpose_kernel<<<HW / TP_PIX, 256>>>(img);

    dim3 grid(W / TILE, H / TILE);
    recon_scatter<<<grid, THREADS>>>(offx, offy, out);
}